// round 5
// baseline (speedup 1.0000x reference)
#include <cuda_runtime.h>
#include <cooperative_groups.h>

namespace cg = cooperative_groups;

#define B_DIM 256
#define N_DIM 2048
#define D_DIM 128
#define CLUSTER 8
#define ROWS_PER_CTA (N_DIM / CLUSTER)          // 256 rows
#define THREADS 512
#define WARPS (THREADS / 32)                    // 16
#define ROWS_PER_WARP (ROWS_PER_CTA / WARPS)    // 16
#define F4_PER_ROW (D_DIM / 4)                  // 32
#define SMEM_F4 (ROWS_PER_CTA * F4_PER_ROW)     // 8192 float4 = 128 KB
#define DYN_SMEM_BYTES (SMEM_F4 * 16)

// Dynamic smem: the 256x128 ctx slice for this CTA's rank.
extern __shared__ float4 s_ctx4[];

// ---------------------------------------------------------------------------
// Fused kernel: one cluster of 8 CTAs per batch.
//   Phase 0: stage ctx[b, rank*256 : (rank+1)*256, :] into smem (float4 copy)
//   Phase 1: per-row dot with Wc (warp per row, from smem), scores = 64*dot
//            (tgt_term and bias are per-batch constants -> cancel in softmax)
//   Phase 2: cluster-wide softmax stats (max, sum) via DSMEM exchange
//   Phase 3: out = attn * ctx, read from smem, streamed to gmem
// ctx is read from DRAM exactly ONCE.
// ---------------------------------------------------------------------------
__global__ void __cluster_dims__(CLUSTER, 1, 1) __launch_bounds__(THREADS, 1)
fused_hop_kernel(const float* __restrict__ ctx,
                 const float* __restrict__ W,
                 float* __restrict__ out)
{
    __shared__ float s_scores[ROWS_PER_CTA];
    __shared__ float s_red[WARPS];
    __shared__ float s_gather[CLUSTER];
    __shared__ float s_stat[2];   // [0]=local max, [1]=local exp-sum (DSMEM-visible)

    cg::cluster_group cluster = cg::this_cluster();
    const int tid  = threadIdx.x;
    const int wid  = tid >> 5;
    const int lane = tid & 31;
    const unsigned rank = cluster.block_rank();
    const int b = blockIdx.x / CLUSTER;

    const size_t row0 = (size_t)b * N_DIM + (size_t)rank * ROWS_PER_CTA;
    const float4* gsrc = (const float4*)ctx + row0 * F4_PER_ROW;

    // ---- Phase 0: gmem -> smem copy, 16 independent LDG.128 per thread ----
    #pragma unroll
    for (int i = 0; i < SMEM_F4 / THREADS; ++i)
        s_ctx4[tid + i * THREADS] = __ldg(gsrc + tid + i * THREADS);
    __syncthreads();

    // ---- Phase 1: per-row dots from smem (warp per row) ----
    const float4 w4 = __ldg((const float4*)(W + D_DIM) + lane);
    #pragma unroll
    for (int r = 0; r < ROWS_PER_WARP; ++r) {
        const int row = wid * ROWS_PER_WARP + r;
        const float4 c = s_ctx4[row * F4_PER_ROW + lane];
        float s = c.x * w4.x + c.y * w4.y + c.z * w4.z + c.w * w4.w;
        #pragma unroll
        for (int o = 16; o; o >>= 1) s += __shfl_xor_sync(0xffffffffu, s, o);
        if (lane == 0) s_scores[row] = 64.0f * s;   // T * ctx_term
    }
    __syncthreads();

    // ---- Phase 2a: local max over 256 scores ----
    float v = (tid < ROWS_PER_CTA) ? s_scores[tid] : -3.4e38f;
    #pragma unroll
    for (int o = 16; o; o >>= 1) v = fmaxf(v, __shfl_xor_sync(0xffffffffu, v, o));
    if (lane == 0) s_red[wid] = v;
    __syncthreads();
    if (tid == 0) {
        float m = s_red[0];
        #pragma unroll
        for (int i = 1; i < WARPS; ++i) m = fmaxf(m, s_red[i]);
        s_stat[0] = m;
    }
    cluster.sync();

    // gather 8 local maxima via DSMEM
    if (tid < CLUSTER) {
        const float* p = (const float*)cluster.map_shared_rank((void*)s_stat, tid);
        s_gather[tid] = p[0];
    }
    __syncthreads();
    float m = s_gather[0];
    #pragma unroll
    for (int i = 1; i < CLUSTER; ++i) m = fmaxf(m, s_gather[i]);

    // ---- Phase 2b: local sum of exp(score - m) ----
    float e = (tid < ROWS_PER_CTA) ? __expf(s_scores[tid] - m) : 0.0f;
    #pragma unroll
    for (int o = 16; o; o >>= 1) e += __shfl_xor_sync(0xffffffffu, e, o);
    if (lane == 0) s_red[wid] = e;
    __syncthreads();
    if (tid == 0) {
        float s2 = 0.0f;
        #pragma unroll
        for (int i = 0; i < WARPS; ++i) s2 += s_red[i];
        s_stat[1] = s2;
    }
    cluster.sync();

    // gather 8 local sums via DSMEM
    if (tid < CLUSTER) {
        const float* p = (const float*)cluster.map_shared_rank((void*)s_stat, tid);
        s_gather[tid] = p[1];
    }
    __syncthreads();
    float tot = 0.0f;
    #pragma unroll
    for (int i = 0; i < CLUSTER; ++i) tot += s_gather[i];
    const float inv = 1.0f / tot;

    // ---- Phase 3: scale from smem, stream to gmem ----
    float4* gdst = (float4*)out + row0 * F4_PER_ROW;
    #pragma unroll
    for (int r = 0; r < ROWS_PER_WARP; ++r) {
        const int row = wid * ROWS_PER_WARP + r;
        const float a = __expf(s_scores[row] - m) * inv;
        const float4 c = s_ctx4[row * F4_PER_ROW + lane];
        float4 o4;
        o4.x = a * c.x; o4.y = a * c.y; o4.z = a * c.z; o4.w = a * c.w;
        gdst[row * F4_PER_ROW + lane] = o4;
    }

    // No CTA may exit while peers' DSMEM reads of its s_stat could be in flight.
    cluster.sync();
}

// ---------------------------------------------------------------------------
extern "C" void kernel_launch(void* const* d_in, const int* in_sizes, int n_in,
                              void* d_out, int out_size) {
    // d_in[0] = targetsentence_emb (unused: cancels in softmax)
    const float* ctx = (const float*)d_in[1];   // (256, 2048, 128) f32
    const float* W   = (const float*)d_in[2];   // (256,) f32
    // d_in[3] = bias (unused: cancels in softmax)
    float* out = (float*)d_out;                 // (256, 2048, 128) f32

    cudaFuncSetAttribute(fused_hop_kernel,
                         cudaFuncAttributeMaxDynamicSharedMemorySize,
                         DYN_SMEM_BYTES);

    fused_hop_kernel<<<B_DIM * CLUSTER, THREADS, DYN_SMEM_BYTES>>>(ctx, W, out);
}